// round 4
// baseline (speedup 1.0000x reference)
#include <cuda_runtime.h>

// HiPPO-LegS bilinear discretization + sequential scan, N=256, L=1024, ALPHA=0.5.
//
// A lower triangular: strict-lower rank-1 A[i][j] = -r_i r_j, r_i = sqrt(2i+1) (= B),
// diag -(i+1). With K = 2k, w_i = 1/(K+i+1):
//   d_i = (K+i+1)/K, iv = K w, u_i = (K-i) w, e_i/d_i = u_i - w_i, a r iv = r w, hK = 2 f_k
// Closed forms (verified by forward substitution on P1 x = rhs):
//   Ad[i][j] = -a (r_i/d_i)(2 r_j/d_j) prod_{j<m<i} u_m  (i>j);  Ad[j][j] = e_j/d_j; 0 above
//   Bd[i]    = ss (r_i/d_i) prod_{m<i} u_m
// Per time step k (t = k-1):
//   Z_{i+1} = u_i Z_i + v_i,  v_i = 2 r_i w_i (K c_i + f r_i),  Z_0 = 0
//   c'_i = u_i c_i + w_i (r_i (2f - Z_i) - c_i)
//
// Recurrence solved by a SYSTOLIC pipeline on one warp: lane l owns elements
// 8l..8l+7 for all steps; at beat b it processes step t = b-l; the scalar Z
// (and traveling y partial) hop lane-to-lane via one shfl_up per beat. The
// lane skew makes producer(beat b-1, lane l-1, step t) feed consumer
// (beat b, lane l, step t) exactly; Z restarts at 0 per step so lane 0's
// input is constant 0. Beats = L + 31.
//
// Output layout (flattened tuple): [c_all | y_all | GBT_A | GBT_B]

#define HP_L 1024
#define HP_N 256

#define OUT_C  0
#define OUT_Y  262144
#define OUT_GA 263168
#define OUT_GB 67372032

__global__ void __launch_bounds__(256) hippo_fused(
    const float* __restrict__ f,
    const float* __restrict__ init_state,
    const float* __restrict__ Bvec,
    float* __restrict__ out)
{
    if (blockIdx.x == 0) {
        // -------- systolic recurrence + y: warp 0 only --------
        __shared__ float s_f[HP_L];
        const int lane = threadIdx.x;
        if (lane < 32) {
            #pragma unroll
            for (int q = 0; q < HP_L / 32; q++) s_f[lane + 32 * q] = f[lane + 32 * q];
            __syncwarp();

            float c[8], r[8], fi[8], fi1[8];
            #pragma unroll
            for (int e = 0; e < 8; e++) {
                int i = lane * 8 + e;
                r[e]   = Bvec[i];            // r_i = sqrt(2i+1)
                c[e]   = init_state[i];
                fi[e]  = (float)i;
                fi1[e] = (float)(i + 1);
            }
            float* out_c = out + OUT_C;
            float* out_y = out + OUT_Y;

            float Zreg = 0.0f, Yreg = 0.0f;
            // per-lane step counters (t = b - lane), maintained incrementally
            float Kf = (float)(2 * (1 - lane));      // K = 2(t+1) = 2(b-lane+1), b starts 0

            for (int b = 0; b < HP_L + 31; b++) {
                // hop: neighbor's previous-beat outputs (all lanes participate)
                float Zin = __shfl_up_sync(0xffffffffu, Zreg, 1);
                float yin = __shfl_up_sync(0xffffffffu, Yreg, 1);
                if (lane == 0) { Zin = 0.0f; yin = 0.0f; }

                const int t = b - lane;
                if (0 <= t && t < HP_L) {
                    const float fv = s_f[t];
                    const float f2 = fv + fv;        // 2f  (= hK)

                    float Zl = Zin, ysum = 0.0f;
                    #pragma unroll
                    for (int e = 0; e < 8; e++) {
                        float w  = __frcp_rn(Kf + fi1[e]);       // 1/(K+i+1)
                        float u  = (Kf - fi[e]) * w;             // (K-i)w
                        float fr = fv * r[e];
                        float v  = (2.0f * r[e] * w) * fmaf(Kf, c[e], fr);  // 2rw(Kc+fr)
                        float q2 = fmaf(r[e], f2 - Zl, -c[e]);   // r(2f-Z)-c
                        float x  = fmaf(u, c[e], w * q2);        // new state
                        Zl = fmaf(u, Zl, v);
                        c[e] = x;
                        ysum += x;
                    }
                    Zreg = Zl;
                    Yreg = yin + ysum;

                    float4* co = reinterpret_cast<float4*>(out_c + (size_t)t * HP_N + lane * 8);
                    co[0] = make_float4(c[0], c[1], c[2], c[3]);
                    co[1] = make_float4(c[4], c[5], c[6], c[7]);
                    if (lane == 31) out_y[t] = Yreg;   // full sum arrives at last lane
                }
                Kf += 2.0f;
            }
        }
        return;
    }

    // -------- GBT_A / GBT_B for k = blockIdx.x (streaming writes) --------
    __shared__ float s_r[HP_N], s_id[HP_N], s_u[HP_N], s_diag[HP_N];
    const int   k  = blockIdx.x;           // 1..1024
    const int   j  = threadIdx.x;          // column owned by this thread
    const float ik = __fdividef(1.0f, (float)k);
    const float a  = 0.5f * ik;            // ss * ALPHA
    {
        float fj = (float)j;
        float d  = fmaf(a, fj + 1.0f, 1.0f);
        float iv = __fdividef(1.0f, d);
        s_r[j]    = Bvec[j];
        s_id[j]   = iv;
        s_u[j]    = fmaf(-a, fj, 1.0f) * iv;
        s_diag[j] = (2.0f - d) * iv;       // e_j / d_j
    }
    __syncthreads();

    const float cj = 2.0f * s_r[j] * s_id[j];   // 2 r_j / d_j
    float W = 1.0f;                              // prod_{j<m<i} u_m
    float G = 1.0f;                              // (thread 0) prod_{m<i} u_m
    float* ga = out + OUT_GA + (size_t)(k - 1) * (HP_N * HP_N);
    float* gb = out + OUT_GB + (size_t)(k - 1) * HP_N;

    #pragma unroll 4
    for (int i = 0; i < HP_N; i++) {
        float ri = s_r[i], iv = s_id[i], ui = s_u[i];
        float val;
        if (j < i)        val = (-a) * ri * iv * cj * W;
        else if (j == i)  val = s_diag[i];
        else              val = 0.0f;
        __stcs(ga + (size_t)i * HP_N + j, val);   // row-coalesced streaming store
        if (j == 0) { gb[i] = ik * ri * iv * G; G *= ui; }  // ss = 1/k
        if (i > j) W *= ui;
    }
}

extern "C" void kernel_launch(void* const* d_in, const int* in_sizes, int n_in,
                              void* d_out, int out_size) {
    const float* f  = (const float*)d_in[0];   // (L,1)
    const float* s0 = (const float*)d_in[1];   // (N,1) init_state
    // d_in[2] = A (unused: closed-form), d_in[3] = B = r
    const float* Bv = (const float*)d_in[3];
    float* out = (float*)d_out;

    // Single fused launch: block 0 = systolic recurrence + y on one warp;
    // blocks 1..1024 stream GBT_A/GBT_B concurrently (hidden under recurrence).
    hippo_fused<<<1025, 256>>>(f, s0, Bv, out);
}